// round 2
// baseline (speedup 1.0000x reference)
#include <cuda_runtime.h>
#include <math.h>

#define DM 2048
#define NE 8
#define SPR_T 256
#define TS 16
#define CH 256

// ---- device scratch (no allocations allowed) ----
__device__ float g_sumprob[NE];
__device__ float g_count[NE];
__device__ float g_spr_sum;
__device__ float g_xnorm[SPR_T * DM];   // 2 MB, L2-resident
__device__ float g_rnorm[SPR_T * NE];

// ---------------------------------------------------------------------------
__global__ void init_k() {
    int i = threadIdx.x;
    if (i < NE) { g_sumprob[i] = 0.f; g_count[i] = 0.f; }
    if (i == 0) g_spr_sum = 0.f;
}

// ---------------------------------------------------------------------------
// One token per thread. W in dynamic smem (64 KB); all lanes of a warp read
// the SAME W element per step -> broadcast LDS.128, conflict-free.
__global__ void __launch_bounds__(128) router_k(
    const float* __restrict__ x, const float* __restrict__ W,
    float* __restrict__ probs, float* __restrict__ idxo, float* __restrict__ tko,
    int n_tok)
{
    extern __shared__ float4 sW4[];                 // [NE][DM/4]
    const float4* W4 = (const float4*)W;
    for (int i = threadIdx.x; i < NE * DM / 4; i += blockDim.x) sW4[i] = W4[i];
    __syncthreads();

    float lsum[NE], lcnt[NE];
#pragma unroll
    for (int e = 0; e < NE; e++) { lsum[e] = 0.f; lcnt[e] = 0.f; }

    for (int t = blockIdx.x * blockDim.x + threadIdx.x; t < n_tok;
         t += gridDim.x * blockDim.x) {
        const float4* xr = (const float4*)(x + (size_t)t * DM);
        float acc[NE];
#pragma unroll
        for (int e = 0; e < NE; e++) acc[e] = 0.f;
#pragma unroll 2
        for (int c = 0; c < DM / 4; c++) {
            float4 xv = xr[c];
#pragma unroll
            for (int e = 0; e < NE; e++) {
                float4 wv = sW4[e * (DM / 4) + c];
                acc[e] = fmaf(xv.x, wv.x, acc[e]);
                acc[e] = fmaf(xv.y, wv.y, acc[e]);
                acc[e] = fmaf(xv.z, wv.z, acc[e]);
                acc[e] = fmaf(xv.w, wv.w, acc[e]);
            }
        }
        // softmax over 8
        float m = acc[0];
#pragma unroll
        for (int e = 1; e < NE; e++) m = fmaxf(m, acc[e]);
        float p[NE], s = 0.f;
#pragma unroll
        for (int e = 0; e < NE; e++) { p[e] = expf(acc[e] - m); s += p[e]; }
        float inv = 1.f / s;
#pragma unroll
        for (int e = 0; e < NE; e++) { p[e] *= inv; lsum[e] += p[e]; }

        float4* po = (float4*)(probs + (size_t)t * NE);
        po[0] = make_float4(p[0], p[1], p[2], p[3]);
        po[1] = make_float4(p[4], p[5], p[6], p[7]);

        // top-2, lowest-index-first tie-break (strict >)
        int i1 = 0; float v1 = p[0];
#pragma unroll
        for (int e = 1; e < NE; e++) if (p[e] > v1) { v1 = p[e]; i1 = e; }
        int i2 = (i1 == 0) ? 1 : 0; float v2 = p[i2];
#pragma unroll
        for (int e = 0; e < NE; e++)
            if (e != i1 && p[e] > v2) { v2 = p[e]; i2 = e; }
        lcnt[i1] += 1.f; lcnt[i2] += 1.f;

        float rn = 1.f / (v1 + v2);
        ((float2*)idxo)[t] = make_float2((float)i1, (float)i2);
        ((float2*)tko)[t]  = make_float2(v1 * rn, v2 * rn);
    }

    // per-warp reduce -> 16 atomics per warp total
#pragma unroll
    for (int e = 0; e < NE; e++) {
        float s = lsum[e], c = lcnt[e];
#pragma unroll
        for (int o = 16; o > 0; o >>= 1) {
            s += __shfl_down_sync(0xffffffffu, s, o);
            c += __shfl_down_sync(0xffffffffu, c, o);
        }
        if ((threadIdx.x & 31) == 0) {
            atomicAdd(&g_sumprob[e], s);
            atomicAdd(&g_count[e], c);
        }
    }
}

// ---------------------------------------------------------------------------
// One block per sampled token: L2-normalize its x row into g_xnorm and its
// router-prob row into g_rnorm. Reads probs already written by router_k
// (same stream -> ordered).
__global__ void __launch_bounds__(256) spr_gather_k(
    const float* __restrict__ x, const int* __restrict__ spr_idx,
    const float* __restrict__ probs)
{
    int b = blockIdx.x;
    int t = spr_idx[b];
    const float4* xr = (const float4*)(x + (size_t)t * DM);
    float4 a = xr[threadIdx.x];
    float4 bq = xr[threadIdx.x + 256];
    float ss = a.x * a.x + a.y * a.y + a.z * a.z + a.w * a.w
             + bq.x * bq.x + bq.y * bq.y + bq.z * bq.z + bq.w * bq.w;
#pragma unroll
    for (int o = 16; o > 0; o >>= 1) ss += __shfl_down_sync(0xffffffffu, ss, o);
    __shared__ float wred[8];
    __shared__ float s_inv;
    if ((threadIdx.x & 31) == 0) wred[threadIdx.x >> 5] = ss;
    __syncthreads();
    if (threadIdx.x == 0) {
        float tot = 0.f;
#pragma unroll
        for (int w = 0; w < 8; w++) tot += wred[w];
        s_inv = 1.f / fmaxf(sqrtf(tot), 1e-12f);
    }
    __syncthreads();
    float inv = s_inv;
    float4* xo = (float4*)(g_xnorm + (size_t)b * DM);
    xo[threadIdx.x]       = make_float4(a.x * inv, a.y * inv, a.z * inv, a.w * inv);
    xo[threadIdx.x + 256] = make_float4(bq.x * inv, bq.y * inv, bq.z * inv, bq.w * inv);
    if (threadIdx.x == 0) {
        float r[NE], s2 = 0.f;
#pragma unroll
        for (int e = 0; e < NE; e++) {
            r[e] = probs[(size_t)t * NE + e];
            s2 = fmaf(r[e], r[e], s2);
        }
        float ri = 1.f / fmaxf(sqrtf(s2), 1e-12f);
#pragma unroll
        for (int e = 0; e < NE; e++) g_rnorm[b * NE + e] = r[e] * ri;
    }
}

// ---------------------------------------------------------------------------
// 16x16 pair tile per block (256 blocks, 256 threads). Pitch CH+1 so B-row
// reads (stride 257 words) hit distinct banks. 4 accumulators break the
// FFMA RAW chain.
__global__ void __launch_bounds__(256) spr_sim_k() {
    __shared__ float sA[TS][CH + 1];
    __shared__ float sB[TS][CH + 1];
    __shared__ float rA[TS][NE];
    __shared__ float rB[TS][NE];
    int bi = blockIdx.x >> 4, bj = blockIdx.x & 15;
    int i0 = bi * TS, j0 = bj * TS;
    int ti = threadIdx.x >> 4, tj = threadIdx.x & 15;
    if (threadIdx.x < TS * NE) {
        int r = threadIdx.x >> 3, e = threadIdx.x & 7;
        rA[r][e] = g_rnorm[(i0 + r) * NE + e];
        rB[r][e] = g_rnorm[(j0 + r) * NE + e];
    }
    float a0 = 0.f, a1 = 0.f, a2 = 0.f, a3 = 0.f;
    for (int k0 = 0; k0 < DM; k0 += CH) {
        __syncthreads();
        for (int i = threadIdx.x; i < TS * CH / 4; i += 256) {
            int r = i / (CH / 4), c4 = (i % (CH / 4)) * 4;
            float4 va = *(const float4*)&g_xnorm[(size_t)(i0 + r) * DM + k0 + c4];
            float4 vb = *(const float4*)&g_xnorm[(size_t)(j0 + r) * DM + k0 + c4];
            sA[r][c4 + 0] = va.x; sA[r][c4 + 1] = va.y;
            sA[r][c4 + 2] = va.z; sA[r][c4 + 3] = va.w;
            sB[r][c4 + 0] = vb.x; sB[r][c4 + 1] = vb.y;
            sB[r][c4 + 2] = vb.z; sB[r][c4 + 3] = vb.w;
        }
        __syncthreads();
#pragma unroll 8
        for (int c = 0; c < CH; c += 4) {
            a0 = fmaf(sA[ti][c + 0], sB[tj][c + 0], a0);
            a1 = fmaf(sA[ti][c + 1], sB[tj][c + 1], a1);
            a2 = fmaf(sA[ti][c + 2], sB[tj][c + 2], a2);
            a3 = fmaf(sA[ti][c + 3], sB[tj][c + 3], a3);
        }
    }
    float xsim = (a0 + a1) + (a2 + a3);
    float rsim = 0.f;
#pragma unroll
    for (int e = 0; e < NE; e++) rsim = fmaf(rA[ti][e], rB[tj][e], rsim);
    float d = rsim - xsim;
    float v = d * d;
#pragma unroll
    for (int o = 16; o > 0; o >>= 1) v += __shfl_down_sync(0xffffffffu, v, o);
    __shared__ float wsum[8];
    if ((threadIdx.x & 31) == 0) wsum[threadIdx.x >> 5] = v;
    __syncthreads();
    if (threadIdx.x == 0) {
        float s = 0.f;
#pragma unroll
        for (int w = 0; w < 8; w++) s += wsum[w];
        atomicAdd(&g_spr_sum, s);
    }
}

// ---------------------------------------------------------------------------
__global__ void finalize_k(float* __restrict__ aux_out, int n_tok) {
    if (threadIdx.x == 0 && blockIdx.x == 0) {
        float T = (float)n_tok;
        float lb = 0.f, dpsl = 0.f;
        for (int e = 0; e < NE; e++) {
            float Pi = g_sumprob[e] / T;
            float fi = g_count[e] / (T * 2.f);
            lb = fmaf(fi, Pi, lb);
            dpsl += 0.125f * (logf(0.125f) - logf(Pi));
        }
        lb *= (float)NE;
        float spr = g_spr_sum / (float)(SPR_T * SPR_T);
        aux_out[0] = 0.01f * (lb + dpsl + 0.1f * spr);
    }
}

// ---------------------------------------------------------------------------
extern "C" void kernel_launch(void* const* d_in, const int* in_sizes, int n_in,
                              void* d_out, int out_size) {
    const float* x   = (const float*)d_in[0];
    const float* W   = (const float*)d_in[1];
    const int*   spr = (const int*)d_in[2];
    int n_tok = in_sizes[0] / DM;      // 16384

    float* out   = (float*)d_out;
    float* probs = out;                              // [n_tok, 8]
    float* idxo  = out + (size_t)n_tok * NE;         // [n_tok, 2] as float
    float* tko   = idxo + (size_t)n_tok * 2;         // [n_tok, 2]
    float* aux   = tko + (size_t)n_tok * 2;          // scalar

    // 64 KB dynamic smem for W (> 48 KB default cap); idempotent, capture-safe.
    cudaFuncSetAttribute(router_k, cudaFuncAttributeMaxDynamicSharedMemorySize,
                         NE * DM * (int)sizeof(float));

    init_k<<<1, 32>>>();
    router_k<<<128, 128, NE * DM * sizeof(float)>>>(x, W, probs, idxo, tko, n_tok);
    spr_gather_k<<<SPR_T, 256>>>(x, spr, probs);
    spr_sim_k<<<256, 256>>>();
    finalize_k<<<1, 32>>>(aux, n_tok);
}

// round 3
// speedup vs baseline: 1.5005x; 1.5005x over previous
#include <cuda_runtime.h>
#include <math.h>

#define DM 2048
#define NE 8
#define SPR_T 256

// ---- device scratch (no allocations allowed) ----
__device__ float g_sumprob[NE];
__device__ float g_count[NE];
__device__ float g_spr_sum;
__device__ float g_xnorm[SPR_T * DM];   // 2 MB, L2-resident
__device__ float g_rnorm[SPR_T * NE];

// ---------------------------------------------------------------------------
__global__ void init_k() {
    int i = threadIdx.x;
    if (i < NE) { g_sumprob[i] = 0.f; g_count[i] = 0.f; }
    if (i == 0) g_spr_sum = 0.f;
}

// ---------------------------------------------------------------------------
// Split-8 interleaved: 8 threads per token; thread (t,q) handles float4
// columns q, q+8, ... -> warp (4 tokens x 8 lanes) reads 4 contiguous 128B
// lines per LDG (4 wavefronts, coalesced). W smem read: 8 consecutive
// float4 = one 128B window -> 1-phase broadcast LDS.
__global__ void __launch_bounds__(256) router_k(
    const float* __restrict__ x, const float* __restrict__ W,
    float* __restrict__ probs, float* __restrict__ idxo, float* __restrict__ tko,
    int n_tok)
{
    extern __shared__ float4 sW4[];                 // [NE][DM/4] = 64 KB
    const float4* W4 = (const float4*)W;
    for (int i = threadIdx.x; i < NE * DM / 4; i += 256) sW4[i] = W4[i];
    __syncthreads();

    int g = blockIdx.x * 256 + threadIdx.x;
    int t = g >> 3, q = g & 7;

    float acc[NE];
#pragma unroll
    for (int e = 0; e < NE; e++) acc[e] = 0.f;

    bool active = (t < n_tok);
    if (active) {
        const float4* xr = (const float4*)x + (size_t)t * (DM / 4) + q;
#pragma unroll 4
        for (int i = 0; i < DM / 4 / 8; i++) {       // 64 iters
            float4 xv = xr[i * 8];
#pragma unroll
            for (int e = 0; e < NE; e++) {
                float4 wv = sW4[e * (DM / 4) + q + i * 8];
                acc[e] = fmaf(xv.x, wv.x, acc[e]);
                acc[e] = fmaf(xv.y, wv.y, acc[e]);
                acc[e] = fmaf(xv.z, wv.z, acc[e]);
                acc[e] = fmaf(xv.w, wv.w, acc[e]);
            }
        }
    }
    // combine partial dots across the 8 q-lanes of each token
#pragma unroll
    for (int e = 0; e < NE; e++) {
        acc[e] += __shfl_xor_sync(0xffffffffu, acc[e], 1);
        acc[e] += __shfl_xor_sync(0xffffffffu, acc[e], 2);
        acc[e] += __shfl_xor_sync(0xffffffffu, acc[e], 4);
    }

    float lsum[NE], lcnt[NE];
#pragma unroll
    for (int e = 0; e < NE; e++) { lsum[e] = 0.f; lcnt[e] = 0.f; }

    if (active && q == 0) {
        // softmax over 8
        float m = acc[0];
#pragma unroll
        for (int e = 1; e < NE; e++) m = fmaxf(m, acc[e]);
        float p[NE], s = 0.f;
#pragma unroll
        for (int e = 0; e < NE; e++) { p[e] = expf(acc[e] - m); s += p[e]; }
        float inv = 1.f / s;
#pragma unroll
        for (int e = 0; e < NE; e++) { p[e] *= inv; lsum[e] = p[e]; }

        float4* po = (float4*)(probs + (size_t)t * NE);
        po[0] = make_float4(p[0], p[1], p[2], p[3]);
        po[1] = make_float4(p[4], p[5], p[6], p[7]);

        // top-2, lowest-index-first tie-break (strict >)
        int i1 = 0; float v1 = p[0];
#pragma unroll
        for (int e = 1; e < NE; e++) if (p[e] > v1) { v1 = p[e]; i1 = e; }
        int i2 = (i1 == 0) ? 1 : 0; float v2 = p[i2];
#pragma unroll
        for (int e = 0; e < NE; e++)
            if (e != i1 && p[e] > v2) { v2 = p[e]; i2 = e; }
        lcnt[i1] = 1.f; lcnt[i2] = 1.f;

        float rn = 1.f / (v1 + v2);
        ((float2*)idxo)[t] = make_float2((float)i1, (float)i2);
        ((float2*)tko)[t]  = make_float2(v1 * rn, v2 * rn);
    }

    // per-warp reduce -> 16 atomics per warp total
#pragma unroll
    for (int e = 0; e < NE; e++) {
        float s = lsum[e], c = lcnt[e];
#pragma unroll
        for (int o = 16; o > 0; o >>= 1) {
            s += __shfl_down_sync(0xffffffffu, s, o);
            c += __shfl_down_sync(0xffffffffu, c, o);
        }
        if ((threadIdx.x & 31) == 0) {
            atomicAdd(&g_sumprob[e], s);
            atomicAdd(&g_count[e], c);
        }
    }
}

// ---------------------------------------------------------------------------
// One block per sampled token: L2-normalize its x row into g_xnorm and its
// router-prob row into g_rnorm.
__global__ void __launch_bounds__(256) spr_gather_k(
    const float* __restrict__ x, const int* __restrict__ spr_idx,
    const float* __restrict__ probs)
{
    int b = blockIdx.x;
    int t = spr_idx[b];
    const float4* xr = (const float4*)(x + (size_t)t * DM);
    float4 a = xr[threadIdx.x];
    float4 bq = xr[threadIdx.x + 256];
    float ss = a.x * a.x + a.y * a.y + a.z * a.z + a.w * a.w
             + bq.x * bq.x + bq.y * bq.y + bq.z * bq.z + bq.w * bq.w;
#pragma unroll
    for (int o = 16; o > 0; o >>= 1) ss += __shfl_down_sync(0xffffffffu, ss, o);
    __shared__ float wred[8];
    __shared__ float s_inv;
    if ((threadIdx.x & 31) == 0) wred[threadIdx.x >> 5] = ss;
    __syncthreads();
    if (threadIdx.x == 0) {
        float tot = 0.f;
#pragma unroll
        for (int w = 0; w < 8; w++) tot += wred[w];
        s_inv = 1.f / fmaxf(sqrtf(tot), 1e-12f);
    }
    __syncthreads();
    float inv = s_inv;
    float4* xo = (float4*)(g_xnorm + (size_t)b * DM);
    xo[threadIdx.x]       = make_float4(a.x * inv, a.y * inv, a.z * inv, a.w * inv);
    xo[threadIdx.x + 256] = make_float4(bq.x * inv, bq.y * inv, bq.z * inv, bq.w * inv);
    if (threadIdx.x == 0) {
        float r[NE], s2 = 0.f;
#pragma unroll
        for (int e = 0; e < NE; e++) {
            r[e] = probs[(size_t)t * NE + e];
            s2 = fmaf(r[e], r[e], s2);
        }
        float ri = 1.f / fmaxf(sqrtf(s2), 1e-12f);
#pragma unroll
        for (int e = 0; e < NE; e++) g_rnorm[b * NE + e] = r[e] * ri;
    }
}

// ---------------------------------------------------------------------------
// Symmetric tiled gram: only bi<=bj 16x16 tile pairs (136 blocks); off-diag
// contributions weighted x2. 256 threads = 4 k-split groups of 64; each
// group: 8x8 thread grid with 2x2 register tiles over a 512-wide k slice.
#define SCH 64
#define SPITCH 68   // float4-aligned pad; <=2-way bank conflicts
__global__ void __launch_bounds__(256) spr_sim_k() {
    __shared__ float sA[4][16][SPITCH];
    __shared__ float sB[4][16][SPITCH];
    __shared__ float rA[16][NE], rB[16][NE];
    __shared__ float ps[4][256];
    __shared__ float wsum[8];

    // block -> (bi, bj) with bi <= bj
    int idx = blockIdx.x, bi = 0;
    while (idx >= 16 - bi) { idx -= 16 - bi; bi++; }
    int bj = bi + idx;
    int i0 = bi * 16, j0 = bj * 16;
    int tid = threadIdx.x;

    if (tid < 128) {
        int r = tid >> 3, e = tid & 7;
        rA[r][e] = g_rnorm[(i0 + r) * NE + e];
    } else {
        int r = (tid - 128) >> 3, e = tid & 7;
        rB[r][e] = g_rnorm[(j0 + r) * NE + e];
    }

    int gr = tid >> 6;          // k-split group 0..3
    int w  = tid & 63;
    int ti = w >> 3, tj = w & 7;
    int r4 = w >> 2, c16 = (w & 3) * 16;   // staging role: row r4, 64B chunk

    float a00 = 0.f, a01 = 0.f, a10 = 0.f, a11 = 0.f;

    for (int cc = 0; cc < 512 / SCH; cc++) {
        int kb = gr * 512 + cc * SCH;
        __syncthreads();
        {
            const float4* pa = (const float4*)&g_xnorm[(size_t)(i0 + r4) * DM + kb + c16];
            const float4* pb = (const float4*)&g_xnorm[(size_t)(j0 + r4) * DM + kb + c16];
#pragma unroll
            for (int u = 0; u < 4; u++) {
                *(float4*)&sA[gr][r4][c16 + 4 * u] = pa[u];
                *(float4*)&sB[gr][r4][c16 + 4 * u] = pb[u];
            }
        }
        __syncthreads();
#pragma unroll 8
        for (int k = 0; k < SCH; k++) {
            float x0 = sA[gr][2 * ti][k],     x1 = sA[gr][2 * ti + 1][k];
            float y0 = sB[gr][2 * tj][k],     y1 = sB[gr][2 * tj + 1][k];
            a00 = fmaf(x0, y0, a00); a01 = fmaf(x0, y1, a01);
            a10 = fmaf(x1, y0, a10); a11 = fmaf(x1, y1, a11);
        }
    }

    ps[gr][(2 * ti) * 16 + 2 * tj]         = a00;
    ps[gr][(2 * ti) * 16 + 2 * tj + 1]     = a01;
    ps[gr][(2 * ti + 1) * 16 + 2 * tj]     = a10;
    ps[gr][(2 * ti + 1) * 16 + 2 * tj + 1] = a11;
    __syncthreads();

    int i = tid >> 4, j = tid & 15;
    float xsim = ps[0][tid] + ps[1][tid] + ps[2][tid] + ps[3][tid];
    float rsim = 0.f;
#pragma unroll
    for (int e = 0; e < NE; e++) rsim = fmaf(rA[i][e], rB[j][e], rsim);
    float d = rsim - xsim;
    float v = d * d * ((bi == bj) ? 1.f : 2.f);
#pragma unroll
    for (int o = 16; o > 0; o >>= 1) v += __shfl_down_sync(0xffffffffu, v, o);
    if ((tid & 31) == 0) wsum[tid >> 5] = v;
    __syncthreads();
    if (tid == 0) {
        float s = 0.f;
#pragma unroll
        for (int q = 0; q < 8; q++) s += wsum[q];
        atomicAdd(&g_spr_sum, s);
    }
}

// ---------------------------------------------------------------------------
__global__ void finalize_k(float* __restrict__ aux_out, int n_tok) {
    if (threadIdx.x == 0 && blockIdx.x == 0) {
        float T = (float)n_tok;
        float lb = 0.f, dpsl = 0.f;
        for (int e = 0; e < NE; e++) {
            float Pi = g_sumprob[e] / T;
            float fi = g_count[e] / (T * 2.f);
            lb = fmaf(fi, Pi, lb);
            dpsl += 0.125f * (logf(0.125f) - logf(Pi));
        }
        lb *= (float)NE;
        float spr = g_spr_sum / (float)(SPR_T * SPR_T);
        aux_out[0] = 0.01f * (lb + dpsl + 0.1f * spr);
    }
}

// ---------------------------------------------------------------------------
extern "C" void kernel_launch(void* const* d_in, const int* in_sizes, int n_in,
                              void* d_out, int out_size) {
    const float* x   = (const float*)d_in[0];
    const float* W   = (const float*)d_in[1];
    const int*   spr = (const int*)d_in[2];
    int n_tok = in_sizes[0] / DM;      // 16384

    float* out   = (float*)d_out;
    float* probs = out;                              // [n_tok, 8]
    float* idxo  = out + (size_t)n_tok * NE;         // [n_tok, 2] as float
    float* tko   = idxo + (size_t)n_tok * 2;         // [n_tok, 2]
    float* aux   = tko + (size_t)n_tok * 2;          // scalar

    cudaFuncSetAttribute(router_k, cudaFuncAttributeMaxDynamicSharedMemorySize,
                         NE * DM * (int)sizeof(float));

    int nthreads = n_tok * 8;
    int nblocks  = (nthreads + 255) / 256;           // 512

    init_k<<<1, 32>>>();
    router_k<<<nblocks, 256, NE * DM * sizeof(float)>>>(x, W, probs, idxo, tko, n_tok);
    spr_gather_k<<<SPR_T, 256>>>(x, spr, probs);
    spr_sim_k<<<136, 256>>>();
    finalize_k<<<1, 32>>>(aux, n_tok);
}

// round 4
// speedup vs baseline: 2.3072x; 1.5377x over previous
#include <cuda_runtime.h>
#include <math.h>

#define DM 2048
#define NE 8
#define SPR_T 256

// ---- device scratch (no allocations allowed) ----
__device__ float g_sumprob[NE];
__device__ float g_count[NE];
__device__ float g_spr_sum;
__device__ float g_xnorm[SPR_T * DM];       // 2 MB, L2-resident
__device__ float g_rnorm[SPR_T * NE];
__device__ float g_xsimp[544 * 256];        // partial gram tiles (pair x 4 k-slices)

// packed f32x2 FMA (sm_100+; ptxas never auto-fuses, PTX-only)
__device__ __forceinline__ unsigned long long ffma2(
    unsigned long long a, unsigned long long b, unsigned long long c) {
    unsigned long long d;
    asm("fma.rn.f32x2 %0, %1, %2, %3;" : "=l"(d) : "l"(a), "l"(b), "l"(c));
    return d;
}
__device__ __forceinline__ float pk_lo(unsigned long long v) {
    return __uint_as_float((unsigned)v);
}
__device__ __forceinline__ float pk_hi(unsigned long long v) {
    return __uint_as_float((unsigned)(v >> 32));
}

// ---------------------------------------------------------------------------
__global__ void init_k() {
    int i = threadIdx.x;
    if (i < NE) { g_sumprob[i] = 0.f; g_count[i] = 0.f; }
    if (i == 0) g_spr_sum = 0.f;
}

// ---------------------------------------------------------------------------
// 512-thread blocks, grid = n_tok/128 (128 blocks -> ONE wave on 148 SMs).
// Split-8: 8 threads per token; 2 tokens per thread (t0, t0+64) so each W
// smem read feeds 4 packed FMAs. Inner loop per thread-iter:
//   2 LDG.128 (x) + 8 LDS.128 (W, 128B-unique window) + 32 fma.rn.f32x2.
__global__ void __launch_bounds__(512) router_k(
    const float* __restrict__ x, const float* __restrict__ W,
    float* __restrict__ probs, float* __restrict__ idxo, float* __restrict__ tko,
    int n_tok)
{
    extern __shared__ ulonglong2 sW[];               // [NE][512] 16B packs = 64 KB
    const ulonglong2* Wg = (const ulonglong2*)W;
    for (int i = threadIdx.x; i < NE * 512; i += 512) sW[i] = Wg[i];
    __syncthreads();

    int tid = threadIdx.x;
    int pair = tid >> 3, q = tid & 7;                // pair 0..63
    int t0 = blockIdx.x * 128 + pair;
    int t1 = t0 + 64;
    bool act0 = (t0 < n_tok), act1 = (t1 < n_tok);

    unsigned long long a0[NE], a1[NE];
#pragma unroll
    for (int e = 0; e < NE; e++) { a0[e] = 0ull; a1[e] = 0ull; }

    if (act0) {
        const ulonglong2* xr0 = (const ulonglong2*)x + (size_t)t0 * 512 + q;
        const ulonglong2* xr1 = (const ulonglong2*)x + (size_t)t1 * 512 + q;
#pragma unroll 2
        for (int i = 0; i < 64; i++) {
            ulonglong2 xv0 = xr0[i * 8];
            ulonglong2 xv1 = act1 ? xr1[i * 8] : make_ulonglong2(0ull, 0ull);
#pragma unroll
            for (int e = 0; e < NE; e++) {
                ulonglong2 wv = sW[e * 512 + q + i * 8];
                a0[e] = ffma2(xv0.x, wv.x, a0[e]);
                a0[e] = ffma2(xv0.y, wv.y, a0[e]);
                a1[e] = ffma2(xv1.x, wv.x, a1[e]);
                a1[e] = ffma2(xv1.y, wv.y, a1[e]);
            }
        }
    }

    float acc0[NE], acc1[NE];
#pragma unroll
    for (int e = 0; e < NE; e++) {
        acc0[e] = pk_lo(a0[e]) + pk_hi(a0[e]);
        acc1[e] = pk_lo(a1[e]) + pk_hi(a1[e]);
    }
    // combine partial dots across the 8 q-lanes of each token
#pragma unroll
    for (int e = 0; e < NE; e++) {
#pragma unroll
        for (int o = 1; o < 8; o <<= 1) {
            acc0[e] += __shfl_xor_sync(0xffffffffu, acc0[e], o);
            acc1[e] += __shfl_xor_sync(0xffffffffu, acc1[e], o);
        }
    }

    float lsum[NE], lcnt[NE];
#pragma unroll
    for (int e = 0; e < NE; e++) { lsum[e] = 0.f; lcnt[e] = 0.f; }

    if (q == 0) {
#pragma unroll
        for (int tt = 0; tt < 2; tt++) {
            if (tt == 0 ? !act0 : !act1) continue;
            int t = tt == 0 ? t0 : t1;
            float* acc = tt == 0 ? acc0 : acc1;
            float m = acc[0];
#pragma unroll
            for (int e = 1; e < NE; e++) m = fmaxf(m, acc[e]);
            float p[NE], s = 0.f;
#pragma unroll
            for (int e = 0; e < NE; e++) { p[e] = expf(acc[e] - m); s += p[e]; }
            float inv = 1.f / s;
#pragma unroll
            for (int e = 0; e < NE; e++) { p[e] *= inv; lsum[e] += p[e]; }

            float4* po = (float4*)(probs + (size_t)t * NE);
            po[0] = make_float4(p[0], p[1], p[2], p[3]);
            po[1] = make_float4(p[4], p[5], p[6], p[7]);

            int i1 = 0; float v1 = p[0];
#pragma unroll
            for (int e = 1; e < NE; e++) if (p[e] > v1) { v1 = p[e]; i1 = e; }
            int i2 = (i1 == 0) ? 1 : 0; float v2 = p[i2];
#pragma unroll
            for (int e = 0; e < NE; e++)
                if (e != i1 && p[e] > v2) { v2 = p[e]; i2 = e; }
            lcnt[i1] += 1.f; lcnt[i2] += 1.f;

            float rn = 1.f / (v1 + v2);
            ((float2*)idxo)[t] = make_float2((float)i1, (float)i2);
            ((float2*)tko)[t]  = make_float2(v1 * rn, v2 * rn);
        }
    }

    // block-level aux reduction -> 16 atomics per block
    __shared__ float red[16][16];
    float v16[16];
#pragma unroll
    for (int e = 0; e < NE; e++) { v16[e] = lsum[e]; v16[NE + e] = lcnt[e]; }
#pragma unroll
    for (int j = 0; j < 16; j++) {
#pragma unroll
        for (int o = 16; o > 0; o >>= 1)
            v16[j] += __shfl_down_sync(0xffffffffu, v16[j], o);
    }
    if ((tid & 31) == 0) {
#pragma unroll
        for (int j = 0; j < 16; j++) red[tid >> 5][j] = v16[j];
    }
    __syncthreads();
    if (tid < 16) {
        float s = 0.f;
#pragma unroll
        for (int w = 0; w < 16; w++) s += red[w][tid];
        if (tid < NE) atomicAdd(&g_sumprob[tid], s);
        else          atomicAdd(&g_count[tid - NE], s);
    }
}

// ---------------------------------------------------------------------------
// One block per sampled token: L2-normalize x row -> g_xnorm, probs row -> g_rnorm.
__global__ void __launch_bounds__(256) spr_gather_k(
    const float* __restrict__ x, const int* __restrict__ spr_idx,
    const float* __restrict__ probs)
{
    int b = blockIdx.x;
    int t = spr_idx[b];
    const float4* xr = (const float4*)(x + (size_t)t * DM);
    float4 a = xr[threadIdx.x];
    float4 bq = xr[threadIdx.x + 256];
    float ss = a.x * a.x + a.y * a.y + a.z * a.z + a.w * a.w
             + bq.x * bq.x + bq.y * bq.y + bq.z * bq.z + bq.w * bq.w;
#pragma unroll
    for (int o = 16; o > 0; o >>= 1) ss += __shfl_down_sync(0xffffffffu, ss, o);
    __shared__ float wred[8];
    __shared__ float s_inv;
    if ((threadIdx.x & 31) == 0) wred[threadIdx.x >> 5] = ss;
    __syncthreads();
    if (threadIdx.x == 0) {
        float tot = 0.f;
#pragma unroll
        for (int w = 0; w < 8; w++) tot += wred[w];
        s_inv = 1.f / fmaxf(sqrtf(tot), 1e-12f);
    }
    __syncthreads();
    float inv = s_inv;
    float4* xo = (float4*)(g_xnorm + (size_t)b * DM);
    xo[threadIdx.x]       = make_float4(a.x * inv, a.y * inv, a.z * inv, a.w * inv);
    xo[threadIdx.x + 256] = make_float4(bq.x * inv, bq.y * inv, bq.z * inv, bq.w * inv);
    if (threadIdx.x == 0) {
        float r[NE], s2 = 0.f;
#pragma unroll
        for (int e = 0; e < NE; e++) {
            r[e] = probs[(size_t)t * NE + e];
            s2 = fmaf(r[e], r[e], s2);
        }
        float ri = 1.f / fmaxf(sqrtf(s2), 1e-12f);
#pragma unroll
        for (int e = 0; e < NE; e++) g_rnorm[b * NE + e] = r[e] * ri;
    }
}

// ---------------------------------------------------------------------------
// Phase A: partial gram tiles. 136 symmetric 16x16 tile pairs x 4 k-slices
// = 544 blocks (5/SM resident -> one wave, 40 warps/SM). 256 threads = 4
// internal k-groups of 64; 8x8 thread grid with 2x2 register tiles.
__global__ void __launch_bounds__(256) spr_simA_k() {
    __shared__ float sA[4][16][68];
    __shared__ float sB[4][16][68];
    __shared__ float ps[4][256];

    int pair = blockIdx.x >> 2, ks = blockIdx.x & 3;
    int idx = pair, bi = 0;
    while (idx >= 16 - bi) { idx -= 16 - bi; bi++; }
    int bj = bi + idx;
    int i0 = bi * 16, j0 = bj * 16;
    int tid = threadIdx.x;

    int gr = tid >> 6;                  // k-group 0..3 (128 k each)
    int w  = tid & 63;
    int ti = w >> 3, tj = w & 7;
    int r4 = w >> 2, c16 = (w & 3) * 16;

    float a00 = 0.f, a01 = 0.f, a10 = 0.f, a11 = 0.f;

#pragma unroll
    for (int cc = 0; cc < 2; cc++) {
        int kb = ks * 512 + gr * 128 + cc * 64;
        __syncthreads();
        {
            const float4* pa = (const float4*)&g_xnorm[(size_t)(i0 + r4) * DM + kb + c16];
            const float4* pb = (const float4*)&g_xnorm[(size_t)(j0 + r4) * DM + kb + c16];
#pragma unroll
            for (int u = 0; u < 4; u++) {
                *(float4*)&sA[gr][r4][c16 + 4 * u] = pa[u];
                *(float4*)&sB[gr][r4][c16 + 4 * u] = pb[u];
            }
        }
        __syncthreads();
#pragma unroll 8
        for (int k = 0; k < 64; k++) {
            float x0 = sA[gr][2 * ti][k],     x1 = sA[gr][2 * ti + 1][k];
            float y0 = sB[gr][2 * tj][k],     y1 = sB[gr][2 * tj + 1][k];
            a00 = fmaf(x0, y0, a00); a01 = fmaf(x0, y1, a01);
            a10 = fmaf(x1, y0, a10); a11 = fmaf(x1, y1, a11);
        }
    }

    ps[gr][(2 * ti) * 16 + 2 * tj]         = a00;
    ps[gr][(2 * ti) * 16 + 2 * tj + 1]     = a01;
    ps[gr][(2 * ti + 1) * 16 + 2 * tj]     = a10;
    ps[gr][(2 * ti + 1) * 16 + 2 * tj + 1] = a11;
    __syncthreads();
    g_xsimp[blockIdx.x * 256 + tid] =
        ps[0][tid] + ps[1][tid] + ps[2][tid] + ps[3][tid];
}

// ---------------------------------------------------------------------------
// Phase B: combine the 4 k-slice partials, compute (rsim - xsim)^2, reduce.
__global__ void __launch_bounds__(256) spr_simB_k() {
    int pair = blockIdx.x;
    int idx = pair, bi = 0;
    while (idx >= 16 - bi) { idx -= 16 - bi; bi++; }
    int bj = bi + idx;
    int i0 = bi * 16, j0 = bj * 16;
    int tid = threadIdx.x;
    int i = tid >> 4, j = tid & 15;

    float xsim = g_xsimp[(pair * 4 + 0) * 256 + tid]
               + g_xsimp[(pair * 4 + 1) * 256 + tid]
               + g_xsimp[(pair * 4 + 2) * 256 + tid]
               + g_xsimp[(pair * 4 + 3) * 256 + tid];
    float rsim = 0.f;
#pragma unroll
    for (int e = 0; e < NE; e++)
        rsim = fmaf(g_rnorm[(i0 + i) * NE + e], g_rnorm[(j0 + j) * NE + e], rsim);
    float d = rsim - xsim;
    float v = d * d * ((bi == bj) ? 1.f : 2.f);
#pragma unroll
    for (int o = 16; o > 0; o >>= 1) v += __shfl_down_sync(0xffffffffu, v, o);
    __shared__ float wsum[8];
    if ((tid & 31) == 0) wsum[tid >> 5] = v;
    __syncthreads();
    if (tid == 0) {
        float s = 0.f;
#pragma unroll
        for (int q = 0; q < 8; q++) s += wsum[q];
        atomicAdd(&g_spr_sum, s);
    }
}

// ---------------------------------------------------------------------------
__global__ void finalize_k(float* __restrict__ aux_out, int n_tok) {
    if (threadIdx.x == 0 && blockIdx.x == 0) {
        float T = (float)n_tok;
        float lb = 0.f, dpsl = 0.f;
        for (int e = 0; e < NE; e++) {
            float Pi = g_sumprob[e] / T;
            float fi = g_count[e] / (T * 2.f);
            lb = fmaf(fi, Pi, lb);
            dpsl += 0.125f * (logf(0.125f) - logf(Pi));
        }
        lb *= (float)NE;
        float spr = g_spr_sum / (float)(SPR_T * SPR_T);
        aux_out[0] = 0.01f * (lb + dpsl + 0.1f * spr);
    }
}

// ---------------------------------------------------------------------------
extern "C" void kernel_launch(void* const* d_in, const int* in_sizes, int n_in,
                              void* d_out, int out_size) {
    const float* x   = (const float*)d_in[0];
    const float* W   = (const float*)d_in[1];
    const int*   spr = (const int*)d_in[2];
    int n_tok = in_sizes[0] / DM;      // 16384

    float* out   = (float*)d_out;
    float* probs = out;                              // [n_tok, 8]
    float* idxo  = out + (size_t)n_tok * NE;         // [n_tok, 2] as float
    float* tko   = idxo + (size_t)n_tok * 2;         // [n_tok, 2]
    float* aux   = tko + (size_t)n_tok * 2;          // scalar

    cudaFuncSetAttribute(router_k, cudaFuncAttributeMaxDynamicSharedMemorySize,
                         NE * DM * (int)sizeof(float));

    int nblocks = (n_tok + 127) / 128;               // 128 -> one wave

    init_k<<<1, 32>>>();
    router_k<<<nblocks, 512, NE * DM * sizeof(float)>>>(x, W, probs, idxo, tko, n_tok);
    spr_gather_k<<<SPR_T, 256>>>(x, spr, probs);
    spr_simA_k<<<544, 256>>>();
    spr_simB_k<<<136, 256>>>();
    finalize_k<<<1, 32>>>(aux, n_tok);
}

// round 5
// speedup vs baseline: 2.6501x; 1.1486x over previous
#include <cuda_runtime.h>
#include <math.h>

#define DM 2048
#define NE 8
#define SPR_T 256

// ---- device scratch (no allocations allowed) ----
__device__ float g_sumprob[NE];
__device__ float g_count[NE];
__device__ float g_spr_sum;
__device__ float g_xnorm[SPR_T * DM];       // 2 MB, L2-resident
__device__ float g_rnorm[SPR_T * NE];
__device__ float g_xsimp[544 * 256];        // partial gram tiles (pair x 4 k-slices)

// packed f32x2 FMA (sm_100+; ptxas never auto-fuses, PTX-only)
__device__ __forceinline__ unsigned long long ffma2(
    unsigned long long a, unsigned long long b, unsigned long long c) {
    unsigned long long d;
    asm("fma.rn.f32x2 %0, %1, %2, %3;" : "=l"(d) : "l"(a), "l"(b), "l"(c));
    return d;
}
__device__ __forceinline__ float pk_lo(unsigned long long v) {
    return __uint_as_float((unsigned)v);
}
__device__ __forceinline__ float pk_hi(unsigned long long v) {
    return __uint_as_float((unsigned)(v >> 32));
}

// ---------------------------------------------------------------------------
__global__ void init_k() {
    int i = threadIdx.x;
    if (i < NE) { g_sumprob[i] = 0.f; g_count[i] = 0.f; }
    if (i == 0) g_spr_sum = 0.f;
}

// ---------------------------------------------------------------------------
// 512-thread blocks, 1 token per thread-octet: 64 tokens/block, 256 blocks
// -> 2 blocks resident on most SMs (64KB smem each, 3 fit) = 32 warps/SM of
// latency hiding. Unpredicated unroll-8 body so ptxas front-batches LDG.128.
__global__ void __launch_bounds__(512) router_k(
    const float* __restrict__ x, const float* __restrict__ W,
    float* __restrict__ probs, float* __restrict__ idxo, float* __restrict__ tko,
    int n_tok)
{
    extern __shared__ ulonglong2 sW[];               // [NE][512] 16B packs = 64 KB
    const ulonglong2* Wg = (const ulonglong2*)W;
    for (int i = threadIdx.x; i < NE * 512; i += 512) sW[i] = Wg[i];
    __syncthreads();

    int tid = threadIdx.x;
    int q = tid & 7;
    int t = blockIdx.x * 64 + (tid >> 3);            // always < n_tok (exact grid)

    unsigned long long a0[NE];
#pragma unroll
    for (int e = 0; e < NE; e++) a0[e] = 0ull;

    const ulonglong2* xr = (const ulonglong2*)x + (size_t)t * 512 + q;
#pragma unroll 8
    for (int i = 0; i < 64; i++) {
        ulonglong2 xv = xr[i * 8];
#pragma unroll
        for (int e = 0; e < NE; e++) {
            ulonglong2 wv = sW[e * 512 + q + i * 8];
            a0[e] = ffma2(xv.x, wv.x, a0[e]);
            a0[e] = ffma2(xv.y, wv.y, a0[e]);
        }
    }

    float acc[NE];
#pragma unroll
    for (int e = 0; e < NE; e++) acc[e] = pk_lo(a0[e]) + pk_hi(a0[e]);
    // combine partial dots across the 8 q-lanes of each token
#pragma unroll
    for (int e = 0; e < NE; e++) {
#pragma unroll
        for (int o = 1; o < 8; o <<= 1)
            acc[e] += __shfl_xor_sync(0xffffffffu, acc[e], o);
    }

    float lsum[NE], lcnt[NE];
#pragma unroll
    for (int e = 0; e < NE; e++) { lsum[e] = 0.f; lcnt[e] = 0.f; }

    if (q == 0) {
        float m = acc[0];
#pragma unroll
        for (int e = 1; e < NE; e++) m = fmaxf(m, acc[e]);
        float p[NE], s = 0.f;
#pragma unroll
        for (int e = 0; e < NE; e++) { p[e] = expf(acc[e] - m); s += p[e]; }
        float inv = 1.f / s;
#pragma unroll
        for (int e = 0; e < NE; e++) { p[e] *= inv; lsum[e] = p[e]; }

        float4* po = (float4*)(probs + (size_t)t * NE);
        po[0] = make_float4(p[0], p[1], p[2], p[3]);
        po[1] = make_float4(p[4], p[5], p[6], p[7]);

        // top-2, lowest-index-first tie-break (strict >)
        int i1 = 0; float v1 = p[0];
#pragma unroll
        for (int e = 1; e < NE; e++) if (p[e] > v1) { v1 = p[e]; i1 = e; }
        int i2 = (i1 == 0) ? 1 : 0; float v2 = p[i2];
#pragma unroll
        for (int e = 0; e < NE; e++)
            if (e != i1 && p[e] > v2) { v2 = p[e]; i2 = e; }
        lcnt[i1] = 1.f; lcnt[i2] = 1.f;

        float rn = 1.f / (v1 + v2);
        ((float2*)idxo)[t] = make_float2((float)i1, (float)i2);
        ((float2*)tko)[t]  = make_float2(v1 * rn, v2 * rn);
    }

    // block-level aux reduction -> 16 atomics per block
    __shared__ float red[16][16];
    float v16[16];
#pragma unroll
    for (int e = 0; e < NE; e++) { v16[e] = lsum[e]; v16[NE + e] = lcnt[e]; }
#pragma unroll
    for (int j = 0; j < 16; j++) {
#pragma unroll
        for (int o = 16; o > 0; o >>= 1)
            v16[j] += __shfl_down_sync(0xffffffffu, v16[j], o);
    }
    if ((tid & 31) == 0) {
#pragma unroll
        for (int j = 0; j < 16; j++) red[tid >> 5][j] = v16[j];
    }
    __syncthreads();
    if (tid < 16) {
        float s = 0.f;
#pragma unroll
        for (int w = 0; w < 16; w++) s += red[w][tid];
        if (tid < NE) atomicAdd(&g_sumprob[tid], s);
        else          atomicAdd(&g_count[tid - NE], s);
    }
}

// ---------------------------------------------------------------------------
// One block per sampled token: L2-normalize x row -> g_xnorm, probs row -> g_rnorm.
__global__ void __launch_bounds__(256) spr_gather_k(
    const float* __restrict__ x, const int* __restrict__ spr_idx,
    const float* __restrict__ probs)
{
    int b = blockIdx.x;
    int t = spr_idx[b];
    const float4* xr = (const float4*)(x + (size_t)t * DM);
    float4 a = xr[threadIdx.x];
    float4 bq = xr[threadIdx.x + 256];
    float ss = a.x * a.x + a.y * a.y + a.z * a.z + a.w * a.w
             + bq.x * bq.x + bq.y * bq.y + bq.z * bq.z + bq.w * bq.w;
#pragma unroll
    for (int o = 16; o > 0; o >>= 1) ss += __shfl_down_sync(0xffffffffu, ss, o);
    __shared__ float wred[8];
    __shared__ float s_inv;
    if ((threadIdx.x & 31) == 0) wred[threadIdx.x >> 5] = ss;
    __syncthreads();
    if (threadIdx.x == 0) {
        float tot = 0.f;
#pragma unroll
        for (int w = 0; w < 8; w++) tot += wred[w];
        s_inv = 1.f / fmaxf(sqrtf(tot), 1e-12f);
    }
    __syncthreads();
    float inv = s_inv;
    float4* xo = (float4*)(g_xnorm + (size_t)b * DM);
    xo[threadIdx.x]       = make_float4(a.x * inv, a.y * inv, a.z * inv, a.w * inv);
    xo[threadIdx.x + 256] = make_float4(bq.x * inv, bq.y * inv, bq.z * inv, bq.w * inv);
    if (threadIdx.x == 0) {
        float r[NE], s2 = 0.f;
#pragma unroll
        for (int e = 0; e < NE; e++) {
            r[e] = probs[(size_t)t * NE + e];
            s2 = fmaf(r[e], r[e], s2);
        }
        float ri = 1.f / fmaxf(sqrtf(s2), 1e-12f);
#pragma unroll
        for (int e = 0; e < NE; e++) g_rnorm[b * NE + e] = r[e] * ri;
    }
}

// ---------------------------------------------------------------------------
// Phase A: partial gram tiles, float4-vectorized over k.
// 136 pairs x 4 k-slices = 544 blocks. 256 thr = 4 k-groups of 64 (8x8 grid,
// 2x2 tile over rows {r, r+8}).  Pitch 68 floats => bank start = 4*row mod 32:
// x-reads (4 rows) and y-reads (8 rows) both conflict-free LDS.128.
__global__ void __launch_bounds__(256) spr_simA_k() {
    __shared__ float sA[4][16][68];
    __shared__ float sB[4][16][68];
    __shared__ float ps[4][256];

    int pair = blockIdx.x >> 2, ks = blockIdx.x & 3;
    int idx = pair, bi = 0;
    while (idx >= 16 - bi) { idx -= 16 - bi; bi++; }
    int bj = bi + idx;
    int i0 = bi * 16, j0 = bj * 16;
    int tid = threadIdx.x;

    int gr = tid >> 6;                  // k-group 0..3 (128 k each)
    int w  = tid & 63;
    int ti = w >> 3, tj = w & 7;
    int r4 = w >> 2, c16 = (w & 3) * 16;

    float4 a00 = {0,0,0,0}, a01 = {0,0,0,0}, a10 = {0,0,0,0}, a11 = {0,0,0,0};

#pragma unroll
    for (int cc = 0; cc < 2; cc++) {
        int kb = ks * 512 + gr * 128 + cc * 64;
        __syncthreads();
        {
            const float4* pa = (const float4*)&g_xnorm[(size_t)(i0 + r4) * DM + kb + c16];
            const float4* pb = (const float4*)&g_xnorm[(size_t)(j0 + r4) * DM + kb + c16];
#pragma unroll
            for (int u = 0; u < 4; u++) {
                *(float4*)&sA[gr][r4][c16 + 4 * u] = pa[u];
                *(float4*)&sB[gr][r4][c16 + 4 * u] = pb[u];
            }
        }
        __syncthreads();
#pragma unroll
        for (int k4 = 0; k4 < 16; k4++) {
            float4 x0 = *(const float4*)&sA[gr][ti][k4 * 4];
            float4 x1 = *(const float4*)&sA[gr][ti + 8][k4 * 4];
            float4 y0 = *(const float4*)&sB[gr][tj][k4 * 4];
            float4 y1 = *(const float4*)&sB[gr][tj + 8][k4 * 4];
            a00.x = fmaf(x0.x, y0.x, a00.x); a00.y = fmaf(x0.y, y0.y, a00.y);
            a00.z = fmaf(x0.z, y0.z, a00.z); a00.w = fmaf(x0.w, y0.w, a00.w);
            a01.x = fmaf(x0.x, y1.x, a01.x); a01.y = fmaf(x0.y, y1.y, a01.y);
            a01.z = fmaf(x0.z, y1.z, a01.z); a01.w = fmaf(x0.w, y1.w, a01.w);
            a10.x = fmaf(x1.x, y0.x, a10.x); a10.y = fmaf(x1.y, y0.y, a10.y);
            a10.z = fmaf(x1.z, y0.z, a10.z); a10.w = fmaf(x1.w, y0.w, a10.w);
            a11.x = fmaf(x1.x, y1.x, a11.x); a11.y = fmaf(x1.y, y1.y, a11.y);
            a11.z = fmaf(x1.z, y1.z, a11.z); a11.w = fmaf(x1.w, y1.w, a11.w);
        }
    }

    ps[gr][ti * 16 + tj]             = (a00.x + a00.y) + (a00.z + a00.w);
    ps[gr][ti * 16 + tj + 8]         = (a01.x + a01.y) + (a01.z + a01.w);
    ps[gr][(ti + 8) * 16 + tj]       = (a10.x + a10.y) + (a10.z + a10.w);
    ps[gr][(ti + 8) * 16 + tj + 8]   = (a11.x + a11.y) + (a11.z + a11.w);
    __syncthreads();
    g_xsimp[blockIdx.x * 256 + tid] =
        ps[0][tid] + ps[1][tid] + ps[2][tid] + ps[3][tid];
}

// ---------------------------------------------------------------------------
// Phase B: combine the 4 k-slice partials, compute (rsim - xsim)^2, reduce.
__global__ void __launch_bounds__(256) spr_simB_k() {
    int pair = blockIdx.x;
    int idx = pair, bi = 0;
    while (idx >= 16 - bi) { idx -= 16 - bi; bi++; }
    int bj = bi + idx;
    int i0 = bi * 16, j0 = bj * 16;
    int tid = threadIdx.x;
    int i = tid >> 4, j = tid & 15;

    float xsim = g_xsimp[(pair * 4 + 0) * 256 + tid]
               + g_xsimp[(pair * 4 + 1) * 256 + tid]
               + g_xsimp[(pair * 4 + 2) * 256 + tid]
               + g_xsimp[(pair * 4 + 3) * 256 + tid];
    float rsim = 0.f;
#pragma unroll
    for (int e = 0; e < NE; e++)
        rsim = fmaf(g_rnorm[(i0 + i) * NE + e], g_rnorm[(j0 + j) * NE + e], rsim);
    float d = rsim - xsim;
    float v = d * d * ((bi == bj) ? 1.f : 2.f);
#pragma unroll
    for (int o = 16; o > 0; o >>= 1) v += __shfl_down_sync(0xffffffffu, v, o);
    __shared__ float wsum[8];
    if ((tid & 31) == 0) wsum[tid >> 5] = v;
    __syncthreads();
    if (tid == 0) {
        float s = 0.f;
#pragma unroll
        for (int q = 0; q < 8; q++) s += wsum[q];
        atomicAdd(&g_spr_sum, s);
    }
}

// ---------------------------------------------------------------------------
__global__ void finalize_k(float* __restrict__ aux_out, int n_tok) {
    if (threadIdx.x == 0 && blockIdx.x == 0) {
        float T = (float)n_tok;
        float lb = 0.f, dpsl = 0.f;
        for (int e = 0; e < NE; e++) {
            float Pi = g_sumprob[e] / T;
            float fi = g_count[e] / (T * 2.f);
            lb = fmaf(fi, Pi, lb);
            dpsl += 0.125f * (logf(0.125f) - logf(Pi));
        }
        lb *= (float)NE;
        float spr = g_spr_sum / (float)(SPR_T * SPR_T);
        aux_out[0] = 0.01f * (lb + dpsl + 0.1f * spr);
    }
}

// ---------------------------------------------------------------------------
extern "C" void kernel_launch(void* const* d_in, const int* in_sizes, int n_in,
                              void* d_out, int out_size) {
    const float* x   = (const float*)d_in[0];
    const float* W   = (const float*)d_in[1];
    const int*   spr = (const int*)d_in[2];
    int n_tok = in_sizes[0] / DM;      // 16384

    float* out   = (float*)d_out;
    float* probs = out;                              // [n_tok, 8]
    float* idxo  = out + (size_t)n_tok * NE;         // [n_tok, 2] as float
    float* tko   = idxo + (size_t)n_tok * 2;         // [n_tok, 2]
    float* aux   = tko + (size_t)n_tok * 2;          // scalar

    cudaFuncSetAttribute(router_k, cudaFuncAttributeMaxDynamicSharedMemorySize,
                         NE * DM * (int)sizeof(float));

    int nblocks = (n_tok + 63) / 64;                 // 256 blocks, 64 tok each

    init_k<<<1, 32>>>();
    router_k<<<nblocks, 512, NE * DM * sizeof(float)>>>(x, W, probs, idxo, tko, n_tok);
    spr_gather_k<<<SPR_T, 256>>>(x, spr, probs);
    spr_simA_k<<<544, 256>>>();
    spr_simB_k<<<136, 256>>>();
    finalize_k<<<1, 32>>>(aux, n_tok);
}

// round 8
// speedup vs baseline: 2.7072x; 1.0216x over previous
#include <cuda_runtime.h>
#include <math.h>

#define DM 2048
#define NE 8
#define SPR_T 256
#define NT 8          // 32-row tiles per dim (256/32)
#define KSL 8         // k-slices

// ---- device scratch (no allocations allowed) ----
__device__ float g_sumprob[NE];
__device__ float g_count[NE];
__device__ float g_spr_sum;
__device__ float g_xnorm[SPR_T * DM];       // 2 MB, L2-resident
__device__ float g_rnorm[SPR_T * NE];
__device__ float g_xsimp[288 * 1024];       // partial gram tiles (36 pairs x 8 slices)

// packed f32x2 FMA (sm_100+; ptxas never auto-fuses, PTX-only)
__device__ __forceinline__ unsigned long long ffma2(
    unsigned long long a, unsigned long long b, unsigned long long c) {
    unsigned long long d;
    asm("fma.rn.f32x2 %0, %1, %2, %3;" : "=l"(d) : "l"(a), "l"(b), "l"(c));
    return d;
}
__device__ __forceinline__ float pk_lo(unsigned long long v) {
    return __uint_as_float((unsigned)v);
}
__device__ __forceinline__ float pk_hi(unsigned long long v) {
    return __uint_as_float((unsigned)(v >> 32));
}

// ---------------------------------------------------------------------------
__global__ void init_k() {
    int i = threadIdx.x;
    if (i < NE) { g_sumprob[i] = 0.f; g_count[i] = 0.f; }
    if (i == 0) g_spr_sum = 0.f;
}

// ---------------------------------------------------------------------------
// 512-thread blocks, split-8 (8 lanes per token), 64 tokens/block.
__global__ void __launch_bounds__(512) router_k(
    const float* __restrict__ x, const float* __restrict__ W,
    float* __restrict__ probs, float* __restrict__ idxo, float* __restrict__ tko,
    int n_tok)
{
    extern __shared__ ulonglong2 sW[];               // [NE][512] 16B packs = 64 KB
    const ulonglong2* Wg = (const ulonglong2*)W;
    for (int i = threadIdx.x; i < NE * 512; i += 512) sW[i] = Wg[i];
    __syncthreads();

    int tid = threadIdx.x;
    int q = tid & 7;
    int t = blockIdx.x * 64 + (tid >> 3);            // exact grid: always valid

    unsigned long long a0[NE];
#pragma unroll
    for (int e = 0; e < NE; e++) a0[e] = 0ull;

    const ulonglong2* xr = (const ulonglong2*)x + (size_t)t * 512 + q;
#pragma unroll 8
    for (int i = 0; i < 64; i++) {
        ulonglong2 xv = xr[i * 8];
#pragma unroll
        for (int e = 0; e < NE; e++) {
            ulonglong2 wv = sW[e * 512 + q + i * 8];
            a0[e] = ffma2(xv.x, wv.x, a0[e]);
            a0[e] = ffma2(xv.y, wv.y, a0[e]);
        }
    }

    float acc[NE];
#pragma unroll
    for (int e = 0; e < NE; e++) acc[e] = pk_lo(a0[e]) + pk_hi(a0[e]);
#pragma unroll
    for (int e = 0; e < NE; e++) {
#pragma unroll
        for (int o = 1; o < 8; o <<= 1)
            acc[e] += __shfl_xor_sync(0xffffffffu, acc[e], o);
    }

    float lsum[NE], lcnt[NE];
#pragma unroll
    for (int e = 0; e < NE; e++) { lsum[e] = 0.f; lcnt[e] = 0.f; }

    if (q == 0) {
        float m = acc[0];
#pragma unroll
        for (int e = 1; e < NE; e++) m = fmaxf(m, acc[e]);
        float p[NE], s = 0.f;
#pragma unroll
        for (int e = 0; e < NE; e++) { p[e] = expf(acc[e] - m); s += p[e]; }
        float inv = 1.f / s;
#pragma unroll
        for (int e = 0; e < NE; e++) { p[e] *= inv; lsum[e] = p[e]; }

        float4* po = (float4*)(probs + (size_t)t * NE);
        po[0] = make_float4(p[0], p[1], p[2], p[3]);
        po[1] = make_float4(p[4], p[5], p[6], p[7]);

        // top-2, lowest-index-first tie-break (strict >)
        int i1 = 0; float v1 = p[0];
#pragma unroll
        for (int e = 1; e < NE; e++) if (p[e] > v1) { v1 = p[e]; i1 = e; }
        int i2 = (i1 == 0) ? 1 : 0; float v2 = p[i2];
#pragma unroll
        for (int e = 0; e < NE; e++)
            if (e != i1 && p[e] > v2) { v2 = p[e]; i2 = e; }
        lcnt[i1] = 1.f; lcnt[i2] = 1.f;

        float rn = 1.f / (v1 + v2);
        ((float2*)idxo)[t] = make_float2((float)i1, (float)i2);
        ((float2*)tko)[t]  = make_float2(v1 * rn, v2 * rn);
    }

    // block-level aux reduction -> 16 atomics per block
    __shared__ float red[16][16];
    float v16[16];
#pragma unroll
    for (int e = 0; e < NE; e++) { v16[e] = lsum[e]; v16[NE + e] = lcnt[e]; }
#pragma unroll
    for (int j = 0; j < 16; j++) {
#pragma unroll
        for (int o = 16; o > 0; o >>= 1)
            v16[j] += __shfl_down_sync(0xffffffffu, v16[j], o);
    }
    if ((tid & 31) == 0) {
#pragma unroll
        for (int j = 0; j < 16; j++) red[tid >> 5][j] = v16[j];
    }
    __syncthreads();
    if (tid < 16) {
        float s = 0.f;
#pragma unroll
        for (int w = 0; w < 16; w++) s += red[w][tid];
        if (tid < NE) atomicAdd(&g_sumprob[tid], s);
        else          atomicAdd(&g_count[tid - NE], s);
    }
}

// ---------------------------------------------------------------------------
// One block per sampled token: L2-normalize x row -> g_xnorm, probs row -> g_rnorm.
__global__ void __launch_bounds__(256) spr_gather_k(
    const float* __restrict__ x, const int* __restrict__ spr_idx,
    const float* __restrict__ probs)
{
    int b = blockIdx.x;
    int t = spr_idx[b];
    const float4* xr = (const float4*)(x + (size_t)t * DM);
    float4 a = xr[threadIdx.x];
    float4 bq = xr[threadIdx.x + 256];
    float ss = a.x * a.x + a.y * a.y + a.z * a.z + a.w * a.w
             + bq.x * bq.x + bq.y * bq.y + bq.z * bq.z + bq.w * bq.w;
#pragma unroll
    for (int o = 16; o > 0; o >>= 1) ss += __shfl_down_sync(0xffffffffu, ss, o);
    __shared__ float wred[8];
    __shared__ float s_inv;
    if ((threadIdx.x & 31) == 0) wred[threadIdx.x >> 5] = ss;
    __syncthreads();
    if (threadIdx.x == 0) {
        float tot = 0.f;
#pragma unroll
        for (int w = 0; w < 8; w++) tot += wred[w];
        s_inv = 1.f / fmaxf(sqrtf(tot), 1e-12f);
    }
    __syncthreads();
    float inv = s_inv;
    float4* xo = (float4*)(g_xnorm + (size_t)b * DM);
    xo[threadIdx.x]       = make_float4(a.x * inv, a.y * inv, a.z * inv, a.w * inv);
    xo[threadIdx.x + 256] = make_float4(bq.x * inv, bq.y * inv, bq.z * inv, bq.w * inv);
    if (threadIdx.x == 0) {
        float r[NE], s2 = 0.f;
#pragma unroll
        for (int e = 0; e < NE; e++) {
            r[e] = probs[(size_t)t * NE + e];
            s2 = fmaf(r[e], r[e], s2);
        }
        float ri = 1.f / fmaxf(sqrtf(s2), 1e-12f);
#pragma unroll
        for (int e = 0; e < NE; e++) g_rnorm[b * NE + e] = r[e] * ri;
    }
}

// ---------------------------------------------------------------------------
// Phase A: 32x32 block tiles, 4x4 register tiles (2 B-from-smem per FMA).
// 36 symmetric pairs x 8 k-slices = 288 blocks; 256 thr = 4 k-groups of 64
// (8x8 thread grid), k-slice 256 = group 64 = 2 chunks of 32.
__global__ void __launch_bounds__(256) spr_simA_k() {
    __shared__ float sA[4][32][36];
    __shared__ float sB[4][32][36];
    __shared__ float ps[4][1024];

    int pair = blockIdx.x >> 3, ks = blockIdx.x & 7;
    int idx = pair, bi = 0;
    while (idx >= NT - bi) { idx -= NT - bi; bi++; }
    int bj = bi + idx;
    int i0 = bi * 32, j0 = bj * 32;
    int tid = threadIdx.x;

    int g = tid >> 6;                   // k-group 0..3 (64 k each)
    int w = tid & 63;
    int ti = w >> 3, tj = w & 7;        // 8x8 grid, thread owns 4x4 outputs
    int srow = w >> 1, sc = (w & 1) * 16;

    float acc[4][4];
#pragma unroll
    for (int u = 0; u < 4; u++)
#pragma unroll
        for (int v = 0; v < 4; v++) acc[u][v] = 0.f;

#pragma unroll
    for (int cc = 0; cc < 2; cc++) {
        int kb = ks * 256 + g * 64 + cc * 32;
        __syncthreads();
        {
            const float4* pa = (const float4*)&g_xnorm[(size_t)(i0 + srow) * DM + kb + sc];
            const float4* pb = (const float4*)&g_xnorm[(size_t)(j0 + srow) * DM + kb + sc];
#pragma unroll
            for (int u = 0; u < 4; u++) {
                *(float4*)&sA[g][srow][sc + 4 * u] = pa[u];
                *(float4*)&sB[g][srow][sc + 4 * u] = pb[u];
            }
        }
        __syncthreads();
#pragma unroll
        for (int k4 = 0; k4 < 8; k4++) {
            float4 av[4], bv[4];
#pragma unroll
            for (int u = 0; u < 4; u++)
                av[u] = *(const float4*)&sA[g][4 * ti + u][k4 * 4];
#pragma unroll
            for (int v = 0; v < 4; v++)
                bv[v] = *(const float4*)&sB[g][4 * tj + v][k4 * 4];
#pragma unroll
            for (int u = 0; u < 4; u++)
#pragma unroll
                for (int v = 0; v < 4; v++) {
                    acc[u][v] = fmaf(av[u].x, bv[v].x, acc[u][v]);
                    acc[u][v] = fmaf(av[u].y, bv[v].y, acc[u][v]);
                    acc[u][v] = fmaf(av[u].z, bv[v].z, acc[u][v]);
                    acc[u][v] = fmaf(av[u].w, bv[v].w, acc[u][v]);
                }
        }
    }

#pragma unroll
    for (int u = 0; u < 4; u++)
#pragma unroll
        for (int v = 0; v < 4; v++)
            ps[g][(4 * ti + u) * 32 + 4 * tj + v] = acc[u][v];
    __syncthreads();

    int o0 = tid * 4;
    float4 r;
    r.x = ps[0][o0 + 0] + ps[1][o0 + 0] + ps[2][o0 + 0] + ps[3][o0 + 0];
    r.y = ps[0][o0 + 1] + ps[1][o0 + 1] + ps[2][o0 + 1] + ps[3][o0 + 1];
    r.z = ps[0][o0 + 2] + ps[1][o0 + 2] + ps[2][o0 + 2] + ps[3][o0 + 2];
    r.w = ps[0][o0 + 3] + ps[1][o0 + 3] + ps[2][o0 + 3] + ps[3][o0 + 3];
    *(float4*)&g_xsimp[(size_t)blockIdx.x * 1024 + o0] = r;
}

// ---------------------------------------------------------------------------
// Phase B: combine 8 k-slice partials per 32x32 tile, (rsim - xsim)^2, reduce.
__global__ void __launch_bounds__(256) spr_simB_k() {
    int pair = blockIdx.x;
    int idx = pair, bi = 0;
    while (idx >= NT - bi) { idx -= NT - bi; bi++; }
    int bj = bi + idx;
    int i0 = bi * 32, j0 = bj * 32;
    int tid = threadIdx.x;
    int o0 = tid * 4;

    float v = 0.f;
#pragma unroll
    for (int u = 0; u < 4; u++) {
        int o = o0 + u;
        int i = o >> 5, j = o & 31;
        float xsim = 0.f;
#pragma unroll
        for (int s = 0; s < KSL; s++)
            xsim += g_xsimp[(size_t)(pair * KSL + s) * 1024 + o];
        float rsim = 0.f;
#pragma unroll
        for (int e = 0; e < NE; e++)
            rsim = fmaf(g_rnorm[(i0 + i) * NE + e], g_rnorm[(j0 + j) * NE + e], rsim);
        float d = rsim - xsim;
        v = fmaf(d, d, v);
    }
    v *= (bi == bj) ? 1.f : 2.f;
#pragma unroll
    for (int o = 16; o > 0; o >>= 1) v += __shfl_down_sync(0xffffffffu, v, o);
    __shared__ float wsum[8];
    if ((tid & 31) == 0) wsum[tid >> 5] = v;
    __syncthreads();
    if (tid == 0) {
        float s = 0.f;
#pragma unroll
        for (int q = 0; q < 8; q++) s += wsum[q];
        atomicAdd(&g_spr_sum, s);
    }
}

// ---------------------------------------------------------------------------
__global__ void finalize_k(float* __restrict__ aux_out, int n_tok) {
    if (threadIdx.x == 0 && blockIdx.x == 0) {
        float T = (float)n_tok;
        float lb = 0.f, dpsl = 0.f;
        for (int e = 0; e < NE; e++) {
            float Pi = g_sumprob[e] / T;
            float fi = g_count[e] / (T * 2.f);
            lb = fmaf(fi, Pi, lb);
            dpsl += 0.125f * (logf(0.125f) - logf(Pi));
        }
        lb *= (float)NE;
        float spr = g_spr_sum / (float)(SPR_T * SPR_T);
        aux_out[0] = 0.01f * (lb + dpsl + 0.1f * spr);
    }
}

// ---------------------------------------------------------------------------
extern "C" void kernel_launch(void* const* d_in, const int* in_sizes, int n_in,
                              void* d_out, int out_size) {
    const float* x   = (const float*)d_in[0];
    const float* W   = (const float*)d_in[1];
    const int*   spr = (const int*)d_in[2];
    int n_tok = in_sizes[0] / DM;      // 16384

    float* out   = (float*)d_out;
    float* probs = out;                              // [n_tok, 8]
    float* idxo  = out + (size_t)n_tok * NE;         // [n_tok, 2] as float
    float* tko   = idxo + (size_t)n_tok * 2;         // [n_tok, 2]
    float* aux   = tko + (size_t)n_tok * 2;          // scalar

    cudaFuncSetAttribute(router_k, cudaFuncAttributeMaxDynamicSharedMemorySize,
                         NE * DM * (int)sizeof(float));

    int nblocks = (n_tok + 63) / 64;                 // 256 blocks, 64 tok each

    init_k<<<1, 32>>>();
    router_k<<<nblocks, 512, NE * DM * sizeof(float)>>>(x, W, probs, idxo, tko, n_tok);
    spr_gather_k<<<SPR_T, 256>>>(x, spr, probs);
    spr_simA_k<<<36 * KSL, 256>>>();
    spr_simB_k<<<36, 256>>>();
    finalize_k<<<1, 32>>>(aux, n_tok);
}

// round 9
// speedup vs baseline: 2.8654x; 1.0584x over previous
#include <cuda_runtime.h>
#include <math.h>

#define DM 2048
#define NE 8
#define SPR_T 256
#define NT 8          // 32-row tiles per dim (256/32)
#define KSL 8         // k-slices
#define PITCH 40      // smem row pitch: bank-group = (2*row + c') mod 8

// ---- device scratch (no allocations allowed) ----
__device__ float g_bsum[256 * 16];          // per-router-block partials (8 sumprob + 8 count)
__device__ float g_sprpart[36];             // per-pair SPR partials
__device__ float g_xnorm[SPR_T * DM];       // 2 MB, L2-resident
__device__ float g_rnorm[SPR_T * NE];
__device__ float g_xsimp[288 * 1024];       // partial gram tiles (36 pairs x 8 slices)

// packed f32x2 FMA (sm_100+; ptxas never auto-fuses, PTX-only)
__device__ __forceinline__ unsigned long long ffma2(
    unsigned long long a, unsigned long long b, unsigned long long c) {
    unsigned long long d;
    asm("fma.rn.f32x2 %0, %1, %2, %3;" : "=l"(d) : "l"(a), "l"(b), "l"(c));
    return d;
}
__device__ __forceinline__ float pk_lo(unsigned long long v) {
    return __uint_as_float((unsigned)v);
}
__device__ __forceinline__ float pk_hi(unsigned long long v) {
    return __uint_as_float((unsigned)(v >> 32));
}

// ---------------------------------------------------------------------------
// 512-thread blocks, split-8 (8 lanes per token), 64 tokens/block.
__global__ void __launch_bounds__(512) router_k(
    const float* __restrict__ x, const float* __restrict__ W,
    float* __restrict__ probs, float* __restrict__ idxo, float* __restrict__ tko,
    int n_tok)
{
    extern __shared__ ulonglong2 sW[];               // [NE][512] 16B packs = 64 KB
    const ulonglong2* Wg = (const ulonglong2*)W;
    for (int i = threadIdx.x; i < NE * 512; i += 512) sW[i] = Wg[i];
    __syncthreads();

    int tid = threadIdx.x;
    int q = tid & 7;
    int t = blockIdx.x * 64 + (tid >> 3);            // exact grid: always valid

    unsigned long long a0[NE];
#pragma unroll
    for (int e = 0; e < NE; e++) a0[e] = 0ull;

    const ulonglong2* xr = (const ulonglong2*)x + (size_t)t * 512 + q;
#pragma unroll 8
    for (int i = 0; i < 64; i++) {
        ulonglong2 xv = xr[i * 8];
#pragma unroll
        for (int e = 0; e < NE; e++) {
            ulonglong2 wv = sW[e * 512 + q + i * 8];
            a0[e] = ffma2(xv.x, wv.x, a0[e]);
            a0[e] = ffma2(xv.y, wv.y, a0[e]);
        }
    }

    float acc[NE];
#pragma unroll
    for (int e = 0; e < NE; e++) acc[e] = pk_lo(a0[e]) + pk_hi(a0[e]);
#pragma unroll
    for (int e = 0; e < NE; e++) {
#pragma unroll
        for (int o = 1; o < 8; o <<= 1)
            acc[e] += __shfl_xor_sync(0xffffffffu, acc[e], o);
    }

    float lsum[NE], lcnt[NE];
#pragma unroll
    for (int e = 0; e < NE; e++) { lsum[e] = 0.f; lcnt[e] = 0.f; }

    if (q == 0) {
        float m = acc[0];
#pragma unroll
        for (int e = 1; e < NE; e++) m = fmaxf(m, acc[e]);
        float p[NE], s = 0.f;
#pragma unroll
        for (int e = 0; e < NE; e++) { p[e] = expf(acc[e] - m); s += p[e]; }
        float inv = 1.f / s;
#pragma unroll
        for (int e = 0; e < NE; e++) { p[e] *= inv; lsum[e] = p[e]; }

        float4* po = (float4*)(probs + (size_t)t * NE);
        po[0] = make_float4(p[0], p[1], p[2], p[3]);
        po[1] = make_float4(p[4], p[5], p[6], p[7]);

        // top-2, lowest-index-first tie-break (strict >)
        int i1 = 0; float v1 = p[0];
#pragma unroll
        for (int e = 1; e < NE; e++) if (p[e] > v1) { v1 = p[e]; i1 = e; }
        int i2 = (i1 == 0) ? 1 : 0; float v2 = p[i2];
#pragma unroll
        for (int e = 0; e < NE; e++)
            if (e != i1 && p[e] > v2) { v2 = p[e]; i2 = e; }
        lcnt[i1] = 1.f; lcnt[i2] = 1.f;

        float rn = 1.f / (v1 + v2);
        ((float2*)idxo)[t] = make_float2((float)i1, (float)i2);
        ((float2*)tko)[t]  = make_float2(v1 * rn, v2 * rn);
    }

    // block-level aux reduction -> per-block partial store (no atomics)
    __shared__ float red[16][16];
    float v16[16];
#pragma unroll
    for (int e = 0; e < NE; e++) { v16[e] = lsum[e]; v16[NE + e] = lcnt[e]; }
#pragma unroll
    for (int j = 0; j < 16; j++) {
#pragma unroll
        for (int o = 16; o > 0; o >>= 1)
            v16[j] += __shfl_down_sync(0xffffffffu, v16[j], o);
    }
    if ((tid & 31) == 0) {
#pragma unroll
        for (int j = 0; j < 16; j++) red[tid >> 5][j] = v16[j];
    }
    __syncthreads();
    if (tid < 16) {
        float s = 0.f;
#pragma unroll
        for (int w = 0; w < 16; w++) s += red[w][tid];
        g_bsum[blockIdx.x * 16 + tid] = s;
    }
}

// ---------------------------------------------------------------------------
// One block per sampled token: L2-normalize x row -> g_xnorm, probs row -> g_rnorm.
__global__ void __launch_bounds__(256) spr_gather_k(
    const float* __restrict__ x, const int* __restrict__ spr_idx,
    const float* __restrict__ probs)
{
    int b = blockIdx.x;
    int t = spr_idx[b];
    const float4* xr = (const float4*)(x + (size_t)t * DM);
    float4 a = xr[threadIdx.x];
    float4 bq = xr[threadIdx.x + 256];
    float ss = a.x * a.x + a.y * a.y + a.z * a.z + a.w * a.w
             + bq.x * bq.x + bq.y * bq.y + bq.z * bq.z + bq.w * bq.w;
#pragma unroll
    for (int o = 16; o > 0; o >>= 1) ss += __shfl_down_sync(0xffffffffu, ss, o);
    __shared__ float wred[8];
    __shared__ float s_inv;
    if ((threadIdx.x & 31) == 0) wred[threadIdx.x >> 5] = ss;
    __syncthreads();
    if (threadIdx.x == 0) {
        float tot = 0.f;
#pragma unroll
        for (int w = 0; w < 8; w++) tot += wred[w];
        s_inv = 1.f / fmaxf(sqrtf(tot), 1e-12f);
    }
    __syncthreads();
    float inv = s_inv;
    float4* xo = (float4*)(g_xnorm + (size_t)b * DM);
    xo[threadIdx.x]       = make_float4(a.x * inv, a.y * inv, a.z * inv, a.w * inv);
    xo[threadIdx.x + 256] = make_float4(bq.x * inv, bq.y * inv, bq.z * inv, bq.w * inv);
    if (threadIdx.x == 0) {
        float r[NE], s2 = 0.f;
#pragma unroll
        for (int e = 0; e < NE; e++) {
            r[e] = probs[(size_t)t * NE + e];
            s2 = fmaf(r[e], r[e], s2);
        }
        float ri = 1.f / fmaxf(sqrtf(s2), 1e-12f);
#pragma unroll
        for (int e = 0; e < NE; e++) g_rnorm[b * NE + e] = r[e] * ri;
    }
}

// ---------------------------------------------------------------------------
// Phase A: 32x32 block tiles, 4x4 register tiles.
// Pitch 40 + swizzle c' = (c + (row>>2)) & 7  => bank-group (2*row + c') mod 8:
//   av reads (rows 4ti+u, ti 0..3):  groups (2u + k4 + ti) mod 8 -> 4 distinct, conflict-free
//   bv reads (rows 4tj+v, tj 0..7):  groups (2v + (k4+tj)&7)     -> 8 distinct, conflict-free
__global__ void __launch_bounds__(256) spr_simA_k() {
    __shared__ float sA[4][32][PITCH];
    __shared__ float sB[4][32][PITCH];
    __shared__ float ps[4][1024];

    int pair = blockIdx.x >> 3, ks = blockIdx.x & 7;
    int idx = pair, bi = 0;
    while (idx >= NT - bi) { idx -= NT - bi; bi++; }
    int bj = bi + idx;
    int i0 = bi * 32, j0 = bj * 32;
    int tid = threadIdx.x;

    int g = tid >> 6;                   // k-group 0..3 (64 k each)
    int w = tid & 63;
    int ti = w >> 3, tj = w & 7;        // 8x8 grid, thread owns 4x4 outputs
    int srow = w >> 1, half = w & 1;

    float acc[4][4];
#pragma unroll
    for (int u = 0; u < 4; u++)
#pragma unroll
        for (int v = 0; v < 4; v++) acc[u][v] = 0.f;

#pragma unroll
    for (int cc = 0; cc < 2; cc++) {
        int kb = ks * 256 + g * 64 + cc * 32;
        __syncthreads();
        {
            const float4* pa = (const float4*)&g_xnorm[(size_t)(i0 + srow) * DM + kb + half * 16];
            const float4* pb = (const float4*)&g_xnorm[(size_t)(j0 + srow) * DM + kb + half * 16];
#pragma unroll
            for (int u = 0; u < 4; u++) {
                int cs = ((half * 4 + u) + (srow >> 2)) & 7;
                *(float4*)&sA[g][srow][cs * 4] = pa[u];
                *(float4*)&sB[g][srow][cs * 4] = pb[u];
            }
        }
        __syncthreads();
#pragma unroll
        for (int k4 = 0; k4 < 8; k4++) {
            float4 av[4], bv[4];
#pragma unroll
            for (int u = 0; u < 4; u++)
                av[u] = *(const float4*)&sA[g][4 * ti + u][((k4 + ti) & 7) * 4];
#pragma unroll
            for (int v = 0; v < 4; v++)
                bv[v] = *(const float4*)&sB[g][4 * tj + v][((k4 + tj) & 7) * 4];
#pragma unroll
            for (int u = 0; u < 4; u++)
#pragma unroll
                for (int v = 0; v < 4; v++) {
                    acc[u][v] = fmaf(av[u].x, bv[v].x, acc[u][v]);
                    acc[u][v] = fmaf(av[u].y, bv[v].y, acc[u][v]);
                    acc[u][v] = fmaf(av[u].z, bv[v].z, acc[u][v]);
                    acc[u][v] = fmaf(av[u].w, bv[v].w, acc[u][v]);
                }
        }
    }

#pragma unroll
    for (int u = 0; u < 4; u++)
#pragma unroll
        for (int v = 0; v < 4; v++)
            ps[g][(4 * ti + u) * 32 + 4 * tj + v] = acc[u][v];
    __syncthreads();

    int o0 = tid * 4;
    float4 r;
    r.x = ps[0][o0 + 0] + ps[1][o0 + 0] + ps[2][o0 + 0] + ps[3][o0 + 0];
    r.y = ps[0][o0 + 1] + ps[1][o0 + 1] + ps[2][o0 + 1] + ps[3][o0 + 1];
    r.z = ps[0][o0 + 2] + ps[1][o0 + 2] + ps[2][o0 + 2] + ps[3][o0 + 2];
    r.w = ps[0][o0 + 3] + ps[1][o0 + 3] + ps[2][o0 + 3] + ps[3][o0 + 3];
    *(float4*)&g_xsimp[(size_t)blockIdx.x * 1024 + o0] = r;
}

// ---------------------------------------------------------------------------
// Phase B: combine 8 k-slice partials per 32x32 tile, (rsim - xsim)^2, reduce
// to a per-pair partial (no atomics).
__global__ void __launch_bounds__(256) spr_simB_k() {
    int pair = blockIdx.x;
    int idx = pair, bi = 0;
    while (idx >= NT - bi) { idx -= NT - bi; bi++; }
    int bj = bi + idx;
    int i0 = bi * 32, j0 = bj * 32;
    int tid = threadIdx.x;
    int o0 = tid * 4;

    float v = 0.f;
#pragma unroll
    for (int u = 0; u < 4; u++) {
        int o = o0 + u;
        int i = o >> 5, j = o & 31;
        float xsim = 0.f;
#pragma unroll
        for (int s = 0; s < KSL; s++)
            xsim += g_xsimp[(size_t)(pair * KSL + s) * 1024 + o];
        float rsim = 0.f;
#pragma unroll
        for (int e = 0; e < NE; e++)
            rsim = fmaf(g_rnorm[(i0 + i) * NE + e], g_rnorm[(j0 + j) * NE + e], rsim);
        float d = rsim - xsim;
        v = fmaf(d, d, v);
    }
    v *= (bi == bj) ? 1.f : 2.f;
#pragma unroll
    for (int o = 16; o > 0; o >>= 1) v += __shfl_down_sync(0xffffffffu, v, o);
    __shared__ float wsum[8];
    if ((tid & 31) == 0) wsum[tid >> 5] = v;
    __syncthreads();
    if (tid == 0) {
        float s = 0.f;
#pragma unroll
        for (int q = 0; q < 8; q++) s += wsum[q];
        g_sprpart[pair] = s;
    }
}

// ---------------------------------------------------------------------------
// Reduce per-block router partials + per-pair SPR partials, emit aux loss.
__global__ void __launch_bounds__(256) finalize_k(
    float* __restrict__ aux_out, int n_tok, int nblk)
{
    __shared__ float sm[16][16];
    __shared__ float vals[16];
    int tid = threadIdx.x;
    int v = tid & 15, part = tid >> 4;
    float s = 0.f;
    for (int b = part; b < nblk; b += 16) s += g_bsum[b * 16 + v];
    sm[part][v] = s;
    __syncthreads();
    if (tid < 16) {
        float tot = 0.f;
#pragma unroll
        for (int p = 0; p < 16; p++) tot += sm[p][tid];
        vals[tid] = tot;
    }
    __syncthreads();
    if (tid == 0) {
        float T = (float)n_tok;
        float lb = 0.f, dpsl = 0.f;
        for (int e = 0; e < NE; e++) {
            float Pi = vals[e] / T;
            float fi = vals[NE + e] / (T * 2.f);
            lb = fmaf(fi, Pi, lb);
            dpsl += 0.125f * (logf(0.125f) - logf(Pi));
        }
        lb *= (float)NE;
        float sprs = 0.f;
        for (int p = 0; p < 36; p++) sprs += g_sprpart[p];
        float spr = sprs / (float)(SPR_T * SPR_T);
        aux_out[0] = 0.01f * (lb + dpsl + 0.1f * spr);
    }
}

// ---------------------------------------------------------------------------
extern "C" void kernel_launch(void* const* d_in, const int* in_sizes, int n_in,
                              void* d_out, int out_size) {
    const float* x   = (const float*)d_in[0];
    const float* W   = (const float*)d_in[1];
    const int*   spr = (const int*)d_in[2];
    int n_tok = in_sizes[0] / DM;      // 16384

    float* out   = (float*)d_out;
    float* probs = out;                              // [n_tok, 8]
    float* idxo  = out + (size_t)n_tok * NE;         // [n_tok, 2] as float
    float* tko   = idxo + (size_t)n_tok * 2;         // [n_tok, 2]
    float* aux   = tko + (size_t)n_tok * 2;          // scalar

    cudaFuncSetAttribute(router_k, cudaFuncAttributeMaxDynamicSharedMemorySize,
                         NE * DM * (int)sizeof(float));

    int nblocks = (n_tok + 63) / 64;                 // 256 blocks, 64 tok each

    router_k<<<nblocks, 512, NE * DM * sizeof(float)>>>(x, W, probs, idxo, tko, n_tok);
    spr_gather_k<<<SPR_T, 256>>>(x, spr, probs);
    spr_simA_k<<<36 * KSL, 256>>>();
    spr_simB_k<<<36, 256>>>();
    finalize_k<<<1, 256>>>(aux, n_tok, nblocks);
}